// round 3
// baseline (speedup 1.0000x reference)
#include <cuda_runtime.h>
#include <math.h>

// Problem constants
#define B_  2
#define N_  2048
#define E_  1024
#define H_  16
#define HD_ 64
#define M_TOTAL (B_*N_)          // 4096
#define F3_ (3*HD_)              // 192

// Scratch (device globals: no runtime allocation allowed)
__device__ float g_k[B_*H_*N_*HD_];
__device__ float g_q[B_*H_*N_*HD_];
__device__ float g_v[B_*H_*N_*HD_];
__device__ float g_sa[B_*N_*E_];

// ---------------------------------------------------------------------------
// GEMM1: per-head QKV projection.
// C[r, h, sec*64+col] = sum_e x[r,e] * Wqkv[h,e,sec*64+col] + bqkv
// Block: 64 rows x 64 cols (one of the K/Q/V 64-col sections of one head).
// grid = (M/64, H*3). Output scattered into g_k / g_q / g_v as [B,H,N,64].
// ---------------------------------------------------------------------------
__global__ __launch_bounds__(256) void qkv_kernel(const float* __restrict__ x,
                                                  const float* __restrict__ Wqkv,
                                                  const float* __restrict__ bqkv)
{
    __shared__ float Ats[16][68];   // A transposed: [k][m]
    __shared__ float Ws [16][68];   // B: [k][n]

    const int t  = threadIdx.x;
    const int tx = t & 15, ty = t >> 4;
    const int rowBase = blockIdx.x * 64;
    const int sec = blockIdx.y % 3;        // 0=K, 1=Q, 2=V (jnp.split order!)
    const int h   = blockIdx.y / 3;
    const float* Wh = Wqkv + (size_t)h * E_ * F3_ + sec * HD_;

    const int aRow = t >> 2, aK4 = t & 3;   // A loader mapping
    const int bK   = t >> 4, bC4 = t & 15;  // B loader mapping

    float acc[4][4] = {};

    for (int kt = 0; kt < E_; kt += 16) {
        float4 a4 = *(const float4*)&x [(size_t)(rowBase + aRow) * E_ + kt + aK4 * 4];
        float4 b4 = *(const float4*)&Wh[(size_t)(kt + bK) * F3_ + bC4 * 4];
        __syncthreads();                    // previous compute done with smem
        Ats[aK4*4+0][aRow] = a4.x;
        Ats[aK4*4+1][aRow] = a4.y;
        Ats[aK4*4+2][aRow] = a4.z;
        Ats[aK4*4+3][aRow] = a4.w;
        *(float4*)&Ws[bK][bC4*4] = b4;
        __syncthreads();
        #pragma unroll
        for (int k = 0; k < 16; k++) {
            float4 av = *(const float4*)&Ats[k][ty*4];
            float4 bv = *(const float4*)&Ws [k][tx*4];
            float a_[4] = {av.x, av.y, av.z, av.w};
            float b_[4] = {bv.x, bv.y, bv.z, bv.w};
            #pragma unroll
            for (int i = 0; i < 4; i++)
                #pragma unroll
                for (int j = 0; j < 4; j++)
                    acc[i][j] += a_[i] * b_[j];
        }
    }

    float* dst = (sec == 0) ? g_k : (sec == 1) ? g_q : g_v;
    #pragma unroll
    for (int i = 0; i < 4; i++) {
        int row = rowBase + ty*4 + i;
        int b = row >> 11, n = row & (N_ - 1);
        float* drow = dst + ((size_t)(b * H_ + h) * N_ + n) * HD_;
        #pragma unroll
        for (int j = 0; j < 4; j++) {
            int col = tx*4 + j;
            drow[col] = acc[i][j] + bqkv[h * F3_ + sec * HD_ + col];
        }
    }
}

// ---------------------------------------------------------------------------
// Flash-attention (causal), fp32. One block = one (b,h) x one 64-row Q tile.
// 256 threads: thread t -> query row r = t>>2, group g = t&3.
//   S phase:   thread owns columns c = g + 4*ci (strided -> conflict-free K reads)
//   PV phase:  thread owns dim chunks (g + 4*j)*4 .. +3 (strided float4 chunks
//              -> conflict-free V reads)
// P goes through the K smem buffer between phases.
// ---------------------------------------------------------------------------
#define SMEM_STRIDE 68           // floats per smem row (64 + pad, 16B aligned)
#define ATTN_SMEM (3 * 64 * SMEM_STRIDE * 4)

__global__ __launch_bounds__(256) void attn_kernel()
{
    extern __shared__ float sm[];
    float* Qs  = sm;                       // 64 x 68
    float* KPs = sm + 64 * SMEM_STRIDE;    // K tile, reused for P
    float* Vs  = sm + 2 * 64 * SMEM_STRIDE;

    const int qt = blockIdx.x;             // query tile 0..31
    const int bh = blockIdx.y;             // b*H+h, 0..31
    const int t  = threadIdx.x;
    const int r  = t >> 2;                 // query row in tile
    const int g  = t & 3;

    // ---- load Q tile, pre-scaled by 1/sqrt(HD) ----
    const float* qptr = g_q + ((size_t)bh * N_ + qt * 64) * HD_;
    #pragma unroll
    for (int i = 0; i < 4; i++) {
        int chunk = t + i * 256;           // 0..1023 float4-chunks
        int row = chunk >> 4, c4 = chunk & 15;
        float4 v = *(const float4*)&qptr[row * HD_ + c4 * 4];
        v.x *= 0.125f; v.y *= 0.125f; v.z *= 0.125f; v.w *= 0.125f;
        *(float4*)&Qs[row * SMEM_STRIDE + c4 * 4] = v;
    }

    float  m = -INFINITY, l = 0.f;
    float4 acc[4];
    #pragma unroll
    for (int j = 0; j < 4; j++) acc[j] = make_float4(0.f, 0.f, 0.f, 0.f);

    for (int kt = 0; kt <= qt; kt++) {
        const float* kptr = g_k + ((size_t)bh * N_ + kt * 64) * HD_;
        const float* vptr = g_v + ((size_t)bh * N_ + kt * 64) * HD_;
        __syncthreads();                   // prior PV done reading KPs/Vs
        #pragma unroll
        for (int i = 0; i < 4; i++) {
            int chunk = t + i * 256;
            int row = chunk >> 4, c4 = chunk & 15;
            *(float4*)&KPs[row * SMEM_STRIDE + c4 * 4] =
                *(const float4*)&kptr[row * HD_ + c4 * 4];
            *(float4*)&Vs [row * SMEM_STRIDE + c4 * 4] =
                *(const float4*)&vptr[row * HD_ + c4 * 4];
        }
        __syncthreads();

        // ---- S = Q K^T (thread: 16 strided columns) ----
        float s[16];
        #pragma unroll
        for (int ci = 0; ci < 16; ci++) s[ci] = 0.f;
        #pragma unroll
        for (int d4 = 0; d4 < 16; d4++) {
            float4 q4 = *(const float4*)&Qs[r * SMEM_STRIDE + d4 * 4];
            #pragma unroll
            for (int ci = 0; ci < 16; ci++) {
                int c = g + 4 * ci;
                float4 k4 = *(const float4*)&KPs[c * SMEM_STRIDE + d4 * 4];
                s[ci] += q4.x * k4.x + q4.y * k4.y + q4.z * k4.z + q4.w * k4.w;
            }
        }
        if (kt == qt) {                    // causal mask on diagonal tile
            #pragma unroll
            for (int ci = 0; ci < 16; ci++)
                if (g + 4 * ci > r) s[ci] = -1e30f;
        }

        // ---- online softmax (reduce across the 4 g-lanes of each row) ----
        float tm = s[0];
        #pragma unroll
        for (int ci = 1; ci < 16; ci++) tm = fmaxf(tm, s[ci]);
        tm = fmaxf(tm, __shfl_xor_sync(0xffffffffu, tm, 1));
        tm = fmaxf(tm, __shfl_xor_sync(0xffffffffu, tm, 2));
        float nm = fmaxf(m, tm);
        float corr = __expf(m - nm);       // m=-inf first iter -> 0
        float p[16];
        float ls = 0.f;
        #pragma unroll
        for (int ci = 0; ci < 16; ci++) {
            p[ci] = __expf(s[ci] - nm);
            ls += p[ci];
        }
        ls += __shfl_xor_sync(0xffffffffu, ls, 1);
        ls += __shfl_xor_sync(0xffffffffu, ls, 2);
        l = l * corr + ls;
        m = nm;
        #pragma unroll
        for (int j = 0; j < 4; j++) {
            acc[j].x *= corr; acc[j].y *= corr; acc[j].z *= corr; acc[j].w *= corr;
        }

        __syncthreads();                   // all S reads of K done
        #pragma unroll
        for (int ci = 0; ci < 16; ci++)
            KPs[r * SMEM_STRIDE + g + 4 * ci] = p[ci];
        __syncthreads();

        // ---- acc += P V (thread: 4 strided float4 chunks of dims) ----
        #pragma unroll 8
        for (int c = 0; c < 64; c++) {
            float pv = KPs[r * SMEM_STRIDE + c];
            #pragma unroll
            for (int j = 0; j < 4; j++) {
                float4 v4 = *(const float4*)&Vs[c * SMEM_STRIDE + (g + 4 * j) * 4];
                acc[j].x += pv * v4.x; acc[j].y += pv * v4.y;
                acc[j].z += pv * v4.z; acc[j].w += pv * v4.w;
            }
        }
    }

    // ---- normalize + write to g_sa[b, n, h*64 + d] ----
    float inv = 1.f / l;
    int b = bh >> 4, h = bh & (H_ - 1);
    int n = qt * 64 + r;
    float* orow = g_sa + ((size_t)(b * N_ + n)) * E_ + h * HD_;
    #pragma unroll
    for (int j = 0; j < 4; j++) {
        float4 o;
        o.x = acc[j].x * inv; o.y = acc[j].y * inv;
        o.z = acc[j].z * inv; o.w = acc[j].w * inv;
        *(float4*)&orow[(g + 4 * j) * 4] = o;
    }
}

// ---------------------------------------------------------------------------
// GEMM2: out = g_sa @ Wout + bout.  4096 x 1024 x 1024.
// ---------------------------------------------------------------------------
__global__ __launch_bounds__(256) void out_kernel(const float* __restrict__ Wout,
                                                  const float* __restrict__ bout,
                                                  float* __restrict__ out)
{
    __shared__ float Ats[16][68];
    __shared__ float Ws [16][68];

    const int t  = threadIdx.x;
    const int tx = t & 15, ty = t >> 4;
    const int rowBase = blockIdx.x * 64;
    const int colBase = blockIdx.y * 64;

    const int aRow = t >> 2, aK4 = t & 3;
    const int bK   = t >> 4, bC4 = t & 15;

    float acc[4][4] = {};

    for (int kt = 0; kt < E_; kt += 16) {
        float4 a4 = *(const float4*)&g_sa[(size_t)(rowBase + aRow) * E_ + kt + aK4 * 4];
        float4 b4 = *(const float4*)&Wout[(size_t)(kt + bK) * E_ + colBase + bC4 * 4];
        __syncthreads();
        Ats[aK4*4+0][aRow] = a4.x;
        Ats[aK4*4+1][aRow] = a4.y;
        Ats[aK4*4+2][aRow] = a4.z;
        Ats[aK4*4+3][aRow] = a4.w;
        *(float4*)&Ws[bK][bC4*4] = b4;
        __syncthreads();
        #pragma unroll
        for (int k = 0; k < 16; k++) {
            float4 av = *(const float4*)&Ats[k][ty*4];
            float4 bv = *(const float4*)&Ws [k][tx*4];
            float a_[4] = {av.x, av.y, av.z, av.w};
            float b_[4] = {bv.x, bv.y, bv.z, bv.w};
            #pragma unroll
            for (int i = 0; i < 4; i++)
                #pragma unroll
                for (int j = 0; j < 4; j++)
                    acc[i][j] += a_[i] * b_[j];
        }
    }

    #pragma unroll
    for (int i = 0; i < 4; i++) {
        int row = rowBase + ty*4 + i;
        float* orow = out + (size_t)row * E_;
        #pragma unroll
        for (int j = 0; j < 4; j++) {
            int col = colBase + tx*4 + j;
            orow[col] = acc[i][j] + bout[col];
        }
    }
}

// ---------------------------------------------------------------------------
extern "C" void kernel_launch(void* const* d_in, const int* in_sizes, int n_in,
                              void* d_out, int out_size)
{
    const float* x    = (const float*)d_in[0];   // [2,2048,1024]
    const float* Wqkv = (const float*)d_in[1];   // [16,1024,192]
    const float* bqkv = (const float*)d_in[2];   // [16,192]
    const float* Wout = (const float*)d_in[3];   // [1024,1024]
    const float* bout = (const float*)d_in[4];   // [1024]
    float* out = (float*)d_out;

    cudaFuncSetAttribute(attn_kernel,
                         cudaFuncAttributeMaxDynamicSharedMemorySize, ATTN_SMEM);

    qkv_kernel<<<dim3(M_TOTAL / 64, H_ * 3), 256>>>(x, Wqkv, bqkv);
    attn_kernel<<<dim3(N_ / 64, B_ * H_), 256, ATTN_SMEM>>>();
    out_kernel<<<dim3(M_TOTAL / 64, E_ / 64), 256>>>(Wout, bout, out);
}

// round 4
// speedup vs baseline: 3.8995x; 3.8995x over previous
#include <cuda_runtime.h>
#include <math.h>

#define B_  2
#define N_  2048
#define E_  1024
#define H_  16
#define HD_ 64
#define M_TOTAL (B_*N_)          // 4096
#define F3_ (3*HD_)              // 192

// Scratch (device globals: no runtime allocation allowed)
__device__ float g_k[B_*H_*N_*HD_];
__device__ float g_q[B_*H_*N_*HD_];
__device__ float g_v[B_*H_*N_*HD_];
__device__ float g_sa[B_*N_*E_];

// ---------------------------------------------------------------------------
// tf32 helpers
// ---------------------------------------------------------------------------
__device__ __forceinline__ unsigned f2t(float f) {
    unsigned u;
    asm("cvt.rna.tf32.f32 %0, %1;" : "=r"(u) : "f"(f));
    return u;
}
__device__ __forceinline__ uint4 f2t4(float4 v) {
    uint4 r; r.x = f2t(v.x); r.y = f2t(v.y); r.z = f2t(v.z); r.w = f2t(v.w);
    return r;
}
// D += A*B, m16n8k8 tf32. A: 4 regs, B: 2 regs, C/D: 4 fp32.
__device__ __forceinline__ void mma8(float* c, const unsigned* a, const unsigned* b) {
    asm volatile(
        "mma.sync.aligned.m16n8k8.row.col.f32.tf32.tf32.f32 "
        "{%0,%1,%2,%3}, {%4,%5,%6,%7}, {%8,%9}, {%0,%1,%2,%3};"
        : "+f"(c[0]), "+f"(c[1]), "+f"(c[2]), "+f"(c[3])
        : "r"(a[0]), "r"(a[1]), "r"(a[2]), "r"(a[3]), "r"(b[0]), "r"(b[1]));
}

// ---------------------------------------------------------------------------
// GEMM1: QKV projection. Block = 64 rows x 192 cols (one full head).
// grid = (64, 16). 256 threads = 8 warps; warp tile 32x48.
// ---------------------------------------------------------------------------
#define QKV_AS 36   // A smem stride (words), 36%32==4 -> conflict-free frags
#define QKV_BS 196  // B smem stride, 196%32==4

__global__ __launch_bounds__(256) void qkv_kernel(const float* __restrict__ x,
                                                  const float* __restrict__ Wqkv,
                                                  const float* __restrict__ bqkv)
{
    __shared__ unsigned As[64][QKV_AS];
    __shared__ unsigned Bs[32][QKV_BS];

    const int t = threadIdx.x, lane = t & 31, w = t >> 5;
    const int warpRow = (w & 1) * 32;
    const int warpCol = (w >> 1) * 48;
    const int rowBase = blockIdx.x * 64;
    const int h = blockIdx.y;
    const float* Wh = Wqkv + (size_t)h * E_ * F3_;

    float c[2][6][4] = {};

    for (int kt = 0; kt < E_; kt += 32) {
        float4 a4[2], b4[6];
        #pragma unroll
        for (int i = 0; i < 2; i++) {
            int idx = t + i * 256, row = idx >> 3, k4 = idx & 7;
            a4[i] = *(const float4*)&x[(size_t)(rowBase + row) * E_ + kt + k4 * 4];
        }
        #pragma unroll
        for (int i = 0; i < 6; i++) {
            int idx = t + i * 256, k = idx / 48, n4 = idx - k * 48;
            b4[i] = *(const float4*)&Wh[(size_t)(kt + k) * F3_ + n4 * 4];
        }
        __syncthreads();
        #pragma unroll
        for (int i = 0; i < 2; i++) {
            int idx = t + i * 256, row = idx >> 3, k4 = idx & 7;
            *(uint4*)&As[row][k4 * 4] = f2t4(a4[i]);
        }
        #pragma unroll
        for (int i = 0; i < 6; i++) {
            int idx = t + i * 256, k = idx / 48, n4 = idx - k * 48;
            *(uint4*)&Bs[k][n4 * 4] = f2t4(b4[i]);
        }
        __syncthreads();

        #pragma unroll
        for (int kk = 0; kk < 4; kk++) {
            unsigned a[2][4], b[6][2];
            const int col = kk * 8 + (lane & 3);
            #pragma unroll
            for (int mi = 0; mi < 2; mi++) {
                int r0 = warpRow + mi * 16 + (lane >> 2);
                a[mi][0] = As[r0][col];     a[mi][1] = As[r0 + 8][col];
                a[mi][2] = As[r0][col + 4]; a[mi][3] = As[r0 + 8][col + 4];
            }
            #pragma unroll
            for (int ni = 0; ni < 6; ni++) {
                int bn = warpCol + ni * 8 + (lane >> 2);
                b[ni][0] = Bs[kk * 8 + (lane & 3)][bn];
                b[ni][1] = Bs[kk * 8 + (lane & 3) + 4][bn];
            }
            #pragma unroll
            for (int mi = 0; mi < 2; mi++)
                #pragma unroll
                for (int ni = 0; ni < 6; ni++)
                    mma8(c[mi][ni], a[mi], b[ni]);
        }
    }

    // epilogue: scatter into g_k/g_q/g_v[b,h,n,64] (sec order: K, Q, V)
    #pragma unroll
    for (int mi = 0; mi < 2; mi++)
        #pragma unroll
        for (int ni = 0; ni < 6; ni++) {
            int col = warpCol + ni * 8 + 2 * (lane & 3);
            int sec = col >> 6, cc = col & 63;
            float* dst = (sec == 0) ? g_k : (sec == 1) ? g_q : g_v;
            float bias0 = bqkv[h * F3_ + col], bias1 = bqkv[h * F3_ + col + 1];
            #pragma unroll
            for (int hf = 0; hf < 2; hf++) {
                int row = rowBase + warpRow + mi * 16 + (lane >> 2) + 8 * hf;
                int b = row >> 11, n = row & (N_ - 1);
                float2 val = { c[mi][ni][2 * hf] + bias0, c[mi][ni][2 * hf + 1] + bias1 };
                *(float2*)&dst[((size_t)(b * H_ + h) * N_ + n) * HD_ + cc] = val;
            }
        }
}

// ---------------------------------------------------------------------------
// Flash attention (causal) with tf32 mma. Block = (qt 64 rows) x (b,h).
// 128 threads = 4 warps; warp owns 16 q-rows. smem stride 68 (68%32==4).
// ---------------------------------------------------------------------------
#define AST 68
#define ATTN_SMEM (4 * 64 * AST * 4)

__global__ __launch_bounds__(128) void attn_kernel()
{
    extern __shared__ unsigned sm[];
    unsigned* Qs = sm;
    unsigned* Ks = sm + 64 * AST;
    unsigned* Vs = sm + 2 * 64 * AST;
    unsigned* Ps = sm + 3 * 64 * AST;

    const int qt = blockIdx.x, bh = blockIdx.y;
    const int t = threadIdx.x, lane = t & 31, w = t >> 5;

    // load + scale + convert Q
    const float* qptr = g_q + ((size_t)bh * N_ + qt * 64) * HD_;
    #pragma unroll
    for (int i = 0; i < 8; i++) {
        int chunk = t + i * 128, row = chunk >> 4, c4 = chunk & 15;
        float4 v = *(const float4*)&qptr[row * HD_ + c4 * 4];
        v.x *= 0.125f; v.y *= 0.125f; v.z *= 0.125f; v.w *= 0.125f;
        *(uint4*)&Qs[row * AST + c4 * 4] = f2t4(v);
    }

    float m[2] = { -INFINITY, -INFINITY }, l[2] = { 0.f, 0.f };
    float o[8][4] = {};

    for (int kt = 0; kt <= qt; kt++) {
        const float* kptr = g_k + ((size_t)bh * N_ + kt * 64) * HD_;
        const float* vptr = g_v + ((size_t)bh * N_ + kt * 64) * HD_;
        __syncthreads();
        #pragma unroll
        for (int i = 0; i < 8; i++) {
            int chunk = t + i * 128, row = chunk >> 4, c4 = chunk & 15;
            *(uint4*)&Ks[row * AST + c4 * 4] = f2t4(*(const float4*)&kptr[row * HD_ + c4 * 4]);
            *(uint4*)&Vs[row * AST + c4 * 4] = f2t4(*(const float4*)&vptr[row * HD_ + c4 * 4]);
        }
        __syncthreads();

        // ---- S = Q K^T ----
        float s[8][4] = {};
        #pragma unroll
        for (int kk = 0; kk < 8; kk++) {
            unsigned a[4];
            const int col = kk * 8 + (lane & 3);
            const int qr = 16 * w + (lane >> 2);
            a[0] = Qs[qr * AST + col];       a[1] = Qs[(qr + 8) * AST + col];
            a[2] = Qs[qr * AST + col + 4];   a[3] = Qs[(qr + 8) * AST + col + 4];
            #pragma unroll
            for (int ni = 0; ni < 8; ni++) {
                unsigned b[2];
                int key = ni * 8 + (lane >> 2);
                b[0] = Ks[key * AST + col];
                b[1] = Ks[key * AST + col + 4];
                mma8(s[ni], a, b);
            }
        }
        if (kt == qt) {
            #pragma unroll
            for (int ni = 0; ni < 8; ni++)
                #pragma unroll
                for (int rg = 0; rg < 4; rg++) {
                    int row = 16 * w + (lane >> 2) + 8 * (rg >> 1);
                    int col = ni * 8 + 2 * (lane & 3) + (rg & 1);
                    if (col > row) s[ni][rg] = -1e30f;
                }
        }

        // ---- online softmax (two rows per thread) ----
        #pragma unroll
        for (int hf = 0; hf < 2; hf++) {
            float tm = s[0][2 * hf];
            #pragma unroll
            for (int ni = 0; ni < 8; ni++) {
                tm = fmaxf(tm, s[ni][2 * hf]);
                tm = fmaxf(tm, s[ni][2 * hf + 1]);
            }
            tm = fmaxf(tm, __shfl_xor_sync(0xffffffffu, tm, 1));
            tm = fmaxf(tm, __shfl_xor_sync(0xffffffffu, tm, 2));
            float nm = fmaxf(m[hf], tm);
            float corr = __expf(m[hf] - nm);
            float ls = 0.f;
            #pragma unroll
            for (int ni = 0; ni < 8; ni++) {
                float p0 = __expf(s[ni][2 * hf] - nm);
                float p1 = __expf(s[ni][2 * hf + 1] - nm);
                s[ni][2 * hf] = p0; s[ni][2 * hf + 1] = p1;
                ls += p0 + p1;
            }
            ls += __shfl_xor_sync(0xffffffffu, ls, 1);
            ls += __shfl_xor_sync(0xffffffffu, ls, 2);
            l[hf] = l[hf] * corr + ls;
            m[hf] = nm;
            #pragma unroll
            for (int ni = 0; ni < 8; ni++) {
                o[ni][2 * hf] *= corr; o[ni][2 * hf + 1] *= corr;
            }
        }

        // ---- P -> smem (warp-private rows), then O += P V ----
        #pragma unroll
        for (int ni = 0; ni < 8; ni++)
            #pragma unroll
            for (int hf = 0; hf < 2; hf++) {
                int row = 16 * w + (lane >> 2) + 8 * hf;
                int col = ni * 8 + 2 * (lane & 3);
                uint2 pv = { f2t(s[ni][2 * hf]), f2t(s[ni][2 * hf + 1]) };
                *(uint2*)&Ps[row * AST + col] = pv;
            }
        __syncwarp();

        #pragma unroll
        for (int kk = 0; kk < 8; kk++) {
            unsigned a[4];
            const int pcol = kk * 8 + (lane & 3);
            const int pr = 16 * w + (lane >> 2);
            a[0] = Ps[pr * AST + pcol];       a[1] = Ps[(pr + 8) * AST + pcol];
            a[2] = Ps[pr * AST + pcol + 4];   a[3] = Ps[(pr + 8) * AST + pcol + 4];
            #pragma unroll
            for (int ni = 0; ni < 8; ni++) {
                unsigned b[2];
                b[0] = Vs[(kk * 8 + (lane & 3)) * AST + ni * 8 + (lane >> 2)];
                b[1] = Vs[(kk * 8 + (lane & 3) + 4) * AST + ni * 8 + (lane >> 2)];
                mma8(o[ni], a, b);
            }
        }
    }

    // ---- normalize + write g_sa[b, n, h*64 + d] ----
    float inv[2] = { 1.f / l[0], 1.f / l[1] };
    int b = bh >> 4, hh = bh & (H_ - 1);
    #pragma unroll
    for (int ni = 0; ni < 8; ni++)
        #pragma unroll
        for (int hf = 0; hf < 2; hf++) {
            int n = qt * 64 + 16 * w + (lane >> 2) + 8 * hf;
            int col = ni * 8 + 2 * (lane & 3);
            float2 val = { o[ni][2 * hf] * inv[hf], o[ni][2 * hf + 1] * inv[hf] };
            *(float2*)&g_sa[((size_t)(b * N_ + n)) * E_ + hh * HD_ + col] = val;
        }
}

// ---------------------------------------------------------------------------
// GEMM2: out = g_sa @ Wout + bout. Block = 64 x 128, 8 warps, warp 32x32.
// grid = (64, 8).
// ---------------------------------------------------------------------------
#define OUT_BS 132  // 132%32==4

__global__ __launch_bounds__(256) void out_kernel(const float* __restrict__ Wout,
                                                  const float* __restrict__ bout,
                                                  float* __restrict__ out)
{
    __shared__ unsigned As[64][QKV_AS];
    __shared__ unsigned Bs[32][OUT_BS];

    const int t = threadIdx.x, lane = t & 31, w = t >> 5;
    const int warpRow = (w & 1) * 32;
    const int warpCol = (w >> 1) * 32;
    const int rowBase = blockIdx.x * 64;
    const int colBase = blockIdx.y * 128;

    float c[2][4][4] = {};

    for (int kt = 0; kt < E_; kt += 32) {
        float4 a4[2], b4[4];
        #pragma unroll
        for (int i = 0; i < 2; i++) {
            int idx = t + i * 256, row = idx >> 3, k4 = idx & 7;
            a4[i] = *(const float4*)&g_sa[(size_t)(rowBase + row) * E_ + kt + k4 * 4];
        }
        #pragma unroll
        for (int i = 0; i < 4; i++) {
            int idx = t + i * 256, k = idx >> 5, n4 = idx & 31;
            b4[i] = *(const float4*)&Wout[(size_t)(kt + k) * E_ + colBase + n4 * 4];
        }
        __syncthreads();
        #pragma unroll
        for (int i = 0; i < 2; i++) {
            int idx = t + i * 256, row = idx >> 3, k4 = idx & 7;
            *(uint4*)&As[row][k4 * 4] = f2t4(a4[i]);
        }
        #pragma unroll
        for (int i = 0; i < 4; i++) {
            int idx = t + i * 256, k = idx >> 5, n4 = idx & 31;
            *(uint4*)&Bs[k][n4 * 4] = f2t4(b4[i]);
        }
        __syncthreads();

        #pragma unroll
        for (int kk = 0; kk < 4; kk++) {
            unsigned a[2][4], b[4][2];
            const int col = kk * 8 + (lane & 3);
            #pragma unroll
            for (int mi = 0; mi < 2; mi++) {
                int r0 = warpRow + mi * 16 + (lane >> 2);
                a[mi][0] = As[r0][col];     a[mi][1] = As[r0 + 8][col];
                a[mi][2] = As[r0][col + 4]; a[mi][3] = As[r0 + 8][col + 4];
            }
            #pragma unroll
            for (int ni = 0; ni < 4; ni++) {
                int bn = warpCol + ni * 8 + (lane >> 2);
                b[ni][0] = Bs[kk * 8 + (lane & 3)][bn];
                b[ni][1] = Bs[kk * 8 + (lane & 3) + 4][bn];
            }
            #pragma unroll
            for (int mi = 0; mi < 2; mi++)
                #pragma unroll
                for (int ni = 0; ni < 4; ni++)
                    mma8(c[mi][ni], a[mi], b[ni]);
        }
    }

    #pragma unroll
    for (int mi = 0; mi < 2; mi++)
        #pragma unroll
        for (int ni = 0; ni < 4; ni++) {
            int col = colBase + warpCol + ni * 8 + 2 * (lane & 3);
            float bias0 = bout[col], bias1 = bout[col + 1];
            #pragma unroll
            for (int hf = 0; hf < 2; hf++) {
                int row = rowBase + warpRow + mi * 16 + (lane >> 2) + 8 * hf;
                float2 val = { c[mi][ni][2 * hf] + bias0, c[mi][ni][2 * hf + 1] + bias1 };
                *(float2*)&out[(size_t)row * E_ + col] = val;
            }
        }
}

// ---------------------------------------------------------------------------
extern "C" void kernel_launch(void* const* d_in, const int* in_sizes, int n_in,
                              void* d_out, int out_size)
{
    const float* x    = (const float*)d_in[0];
    const float* Wqkv = (const float*)d_in[1];
    const float* bqkv = (const float*)d_in[2];
    const float* Wout = (const float*)d_in[3];
    const float* bout = (const float*)d_in[4];
    float* out = (float*)d_out;

    cudaFuncSetAttribute(attn_kernel,
                         cudaFuncAttributeMaxDynamicSharedMemorySize, ATTN_SMEM);

    qkv_kernel<<<dim3(M_TOTAL / 64, H_), 256>>>(x, Wqkv, bqkv);
    attn_kernel<<<dim3(N_ / 64, B_ * H_), 128, ATTN_SMEM>>>();
    out_kernel<<<dim3(M_TOTAL / 64, E_ / 128), 256>>>(Wout, bout, out);
}